// round 5
// baseline (speedup 1.0000x reference)
#include <cuda_runtime.h>
#include <math.h>

// Problem constants (fixed instance)
#define NB    8          // batch
#define LQ    1024       // queries per batch
#define NQ    (NB*LQ)    // 8192 total queries
#define CDIM  256        // d_model
#define NH    8          // heads
#define NP    4          // points
#define HD    32         // head dim
#define IMH   128
#define IMW   128
#define HWPX  (IMH*IMW)  // 16384

// -------- scratch (static __device__; no allocation APIs allowed) --------
__device__ float g_Wcat[CDIM*128];        // [256,128]: cols 0..63 W_off, 64..95 W_attn
__device__ float g_bcat[128];
__device__ float g_P[NQ*128];             // query @ Wcat + bcat
__device__ float g_AGG[NQ*NH*CDIM];       // aggregated 256-d memory per (q,h)
__device__ float g_WINB[NQ*NH];           // in-bounds weight sums (for b_value)

// ---------------------------------------------------------------------------
// k_pack: assemble [W_off | W_attn | 0] into one 256x128 matrix (+ bias)
// ---------------------------------------------------------------------------
__global__ void k_pack(const float* __restrict__ Woff, const float* __restrict__ boff,
                       const float* __restrict__ Wattn, const float* __restrict__ battn) {
    int t = blockIdx.x * blockDim.x + threadIdx.x;   // 0 .. 256*128-1
    int c = t >> 7, j = t & 127;
    float v = 0.f;
    if (j < 64)      v = Woff[c*64 + j];
    else if (j < 96) v = Wattn[c*32 + (j-64)];
    g_Wcat[c*128 + j] = v;
    if (c == 0) {
        float b = 0.f;
        if (j < 64)      b = boff[j];
        else if (j < 96) b = battn[j-64];
        g_bcat[j] = b;
    }
}

// ---------------------------------------------------------------------------
// k_gemm: C[M=8192, N] = A[8192,256] @ B[256,N] + bias.  64x64 tiles, 256 thr,
// 4x4 microtiles, fully vectorized float4 global loads.
// ---------------------------------------------------------------------------
__global__ __launch_bounds__(256) void k_gemm(const float* __restrict__ A,
                                              const float* __restrict__ B, int N,
                                              const float* __restrict__ bias,
                                              float* __restrict__ Cout) {
    __shared__ float As[64][36];     // pad 36: float4-aligned, conflict-free col reads
    __shared__ float Bs[32][64];
    int t  = threadIdx.x;
    int q0 = blockIdx.x * 64;
    int cb = blockIdx.y * 64;
    int tx = t & 15, ty = t >> 4;
    int c0 = tx * 4, r0 = ty * 4;
    float acc[4][4] = {};
    for (int k0 = 0; k0 < 256; k0 += 32) {
        #pragma unroll
        for (int i = 0; i < 2; i++) {       // 512 float4 A-elems
            int e = t + i*256; int row = e >> 3, k4 = e & 7;
            float4 v = *(const float4*)&A[(q0+row)*256 + k0 + k4*4];
            *(float4*)&As[row][k4*4] = v;
        }
        #pragma unroll
        for (int i = 0; i < 2; i++) {       // 512 float4 B-elems
            int e = t + i*256; int kk = e >> 4, j4 = e & 15;
            float4 v = *(const float4*)&B[(k0+kk)*N + cb + j4*4];
            *(float4*)&Bs[kk][j4*4] = v;
        }
        __syncthreads();
        #pragma unroll
        for (int kk = 0; kk < 32; kk++) {
            float4 b4 = *(const float4*)&Bs[kk][c0];
            float a0 = As[r0+0][kk], a1 = As[r0+1][kk], a2 = As[r0+2][kk], a3 = As[r0+3][kk];
            acc[0][0] += a0*b4.x; acc[0][1] += a0*b4.y; acc[0][2] += a0*b4.z; acc[0][3] += a0*b4.w;
            acc[1][0] += a1*b4.x; acc[1][1] += a1*b4.y; acc[1][2] += a1*b4.z; acc[1][3] += a1*b4.w;
            acc[2][0] += a2*b4.x; acc[2][1] += a2*b4.y; acc[2][2] += a2*b4.z; acc[2][3] += a2*b4.w;
            acc[3][0] += a3*b4.x; acc[3][1] += a3*b4.y; acc[3][2] += a3*b4.z; acc[3][3] += a3*b4.w;
        }
        __syncthreads();
    }
    #pragma unroll
    for (int i = 0; i < 4; i++) {
        float4 o;
        o.x = acc[i][0] + bias[cb+c0+0];
        o.y = acc[i][1] + bias[cb+c0+1];
        o.z = acc[i][2] + bias[cb+c0+2];
        o.w = acc[i][3] + bias[cb+c0+3];
        *(float4*)&Cout[(q0+r0+i)*N + cb + c0] = o;
    }
}

// ---------------------------------------------------------------------------
// k_gather: one block (128 thr) per query.
//  - t<32 : softmax + pixel coords for (h,p)
//  - all  : expand 128 bilinear corners, dedup rows into shared hash
//  - t<64 : accumulate distinct rows (MLP=4 float4 loads), 8 head accumulators
// ---------------------------------------------------------------------------
__global__ __launch_bounds__(128) void k_gather(const float* __restrict__ memory,
                                                const float* __restrict__ ref) {
    __shared__ int   s_key[256];
    __shared__ float s_w[256][NH];
    __shared__ int   s_list[128];
    __shared__ int   s_n;
    __shared__ float s_winb[NH];
    __shared__ float s_x[32], s_y[32], s_aw[32];

    int t = threadIdx.x;
    int q = blockIdx.x;
    int n = q >> 10;

    s_key[t] = -1; s_key[t+128] = -1;
    #pragma unroll
    for (int h = 0; h < NH; h++) { s_w[t][h] = 0.f; s_w[t+128][h] = 0.f; }
    if (t == 0) s_n = 0;
    if (t < NH) s_winb[t] = 0.f;

    if (t < 32) {   // per-(h,p) coords + softmax weight
        int h = t >> 2, p = t & 3;
        const float* Pq = &g_P[q*128];
        float rx = ref[q*2+0] * (float)IMW - 0.5f;
        float ry = ref[q*2+1] * (float)IMH - 0.5f;
        float a0 = Pq[64+h*4+0], a1 = Pq[64+h*4+1];
        float a2 = Pq[64+h*4+2], a3 = Pq[64+h*4+3];
        float m = fmaxf(fmaxf(a0,a1), fmaxf(a2,a3));
        float e0 = expf(a0-m), e1 = expf(a1-m), e2 = expf(a2-m), e3 = expf(a3-m);
        float inv = 1.f / (e0+e1+e2+e3);
        float ep = (p == 0) ? e0 : (p == 1) ? e1 : (p == 2) ? e2 : e3;
        s_x[t]  = rx + Pq[h*8 + p*2 + 0];
        s_y[t]  = ry + Pq[h*8 + p*2 + 1];
        s_aw[t] = ep * inv;
    }
    __syncthreads();

    {   // corner expansion + hash insert (all 128 threads, one corner each)
        int hp = t >> 2, corner = t & 3;
        int h = hp >> 2;
        float x  = s_x[hp], y = s_y[hp], aw = s_aw[hp];
        float fx0 = floorf(x), fy0 = floorf(y);
        int ix = (int)fx0 + (corner & 1);
        int iy = (int)fy0 + (corner >> 1);
        float fx = x - fx0, fy = y - fy0;
        float wx = (corner & 1) ? fx : (1.f - fx);
        float wy = (corner & 2) ? fy : (1.f - fy);
        float w = wx * wy * aw;
        if (ix >= 0 && ix < IMW && iy >= 0 && iy < IMH && w != 0.f) {
            int row = iy * IMW + ix;
            int slot = row & 255;
            while (true) {
                int prev = atomicCAS(&s_key[slot], -1, row);
                if (prev == -1 || prev == row) break;
                slot = (slot + 1) & 255;
            }
            atomicAdd(&s_w[slot][h], w);
            atomicAdd(&s_winb[h], w);
        }
    }
    __syncthreads();
    if (s_key[t]     != -1) { int pos = atomicAdd(&s_n, 1); s_list[pos] = t; }
    if (s_key[t+128] != -1) { int pos = atomicAdd(&s_n, 1); s_list[pos] = t+128; }
    __syncthreads();

    int nrows = s_n;
    const float* mem = memory + (size_t)n * HWPX * CDIM;

    if (t < 64) {
        int c = t * 4;                       // channel quad
        float4 acc[NH];
        #pragma unroll
        for (int h = 0; h < NH; h++) acc[h] = make_float4(0.f,0.f,0.f,0.f);

        int i = 0;
        for (; i + 3 < nrows; i += 4) {      // MLP=4: 4 independent LDG.128
            int s0 = s_list[i+0], s1 = s_list[i+1];
            int s2 = s_list[i+2], s3 = s_list[i+3];
            float4 v0 = *(const float4*)&mem[(size_t)s_key[s0]*CDIM + c];
            float4 v1 = *(const float4*)&mem[(size_t)s_key[s1]*CDIM + c];
            float4 v2 = *(const float4*)&mem[(size_t)s_key[s2]*CDIM + c];
            float4 v3 = *(const float4*)&mem[(size_t)s_key[s3]*CDIM + c];
            #pragma unroll
            for (int h = 0; h < NH; h++) {
                float w0 = s_w[s0][h], w1 = s_w[s1][h];
                float w2 = s_w[s2][h], w3 = s_w[s3][h];
                acc[h].x += w0*v0.x + w1*v1.x + w2*v2.x + w3*v3.x;
                acc[h].y += w0*v0.y + w1*v1.y + w2*v2.y + w3*v3.y;
                acc[h].z += w0*v0.z + w1*v1.z + w2*v2.z + w3*v3.z;
                acc[h].w += w0*v0.w + w1*v1.w + w2*v2.w + w3*v3.w;
            }
        }
        for (; i < nrows; i++) {
            int s0 = s_list[i];
            float4 v0 = *(const float4*)&mem[(size_t)s_key[s0]*CDIM + c];
            #pragma unroll
            for (int h = 0; h < NH; h++) {
                float w0 = s_w[s0][h];
                acc[h].x += w0*v0.x; acc[h].y += w0*v0.y;
                acc[h].z += w0*v0.z; acc[h].w += w0*v0.w;
            }
        }
        #pragma unroll
        for (int h = 0; h < NH; h++)
            *(float4*)&g_AGG[((size_t)(q*NH) + h)*CDIM + c] = acc[h];
    }
    if (t < NH) g_WINB[q*NH + t] = s_winb[t];
}

// ---------------------------------------------------------------------------
// k_fuse: per block of 32 queries:
//   stage 1: X[32x256] = blockdiag_h( AGG[q,h,:] @ Wv_h ) + bv*winb   (into smem)
//   stage 2: out[32x256] = X @ Wout + bout
// 256 threads. All global loads float4. smem ~43KB -> 5 blocks/SM.
// ---------------------------------------------------------------------------
__global__ __launch_bounds__(256) void k_fuse(const float* __restrict__ Wv,
                                              const float* __restrict__ bv,
                                              const float* __restrict__ Wout,
                                              const float* __restrict__ bout,
                                              float* __restrict__ out) {
    __shared__ float sX[32][257];        // X tile (pad 257: conflict-free col reads)
    __shared__ float sWinb[32][8];
    __shared__ float As0[32][20];        // AGG tile, even head of pair (k-chunk 16)
    __shared__ float As1[32][20];        // odd head of pair
    __shared__ float Bs[16][64];         // weight chunk (stage1: Wv pair, stage2: Wout)

    int t  = threadIdx.x;
    int q0 = blockIdx.x * 32;
    int tx = t & 15, ty = t >> 4;        // 16 x 16
    int c0 = tx * 4;                     // 4 cols
    int r0 = ty * 2;                     // 2 rows

    // load winb tile (32 x 8)
    {
        int r = t >> 3, h = t & 7;
        sWinb[r][h] = g_WINB[(q0 + r)*NH + h];
    }
    __syncthreads();

    // ---------------- stage 1: 4 head-pairs, 64 output cols each ------------
    #pragma unroll 1
    for (int pair = 0; pair < 4; pair++) {
        float acc[2][4] = {};
        int h0 = pair*2, h1 = pair*2 + 1;
        for (int k0 = 0; k0 < 256; k0 += 16) {
            // As0/As1: 32 rows x 16 k  (128 float4 each)
            if (t < 128) {
                int row = t >> 2, k4 = t & 3;
                float4 v = *(const float4*)&g_AGG[((size_t)(q0+row)*NH + h0)*CDIM + k0 + k4*4];
                *(float4*)&As0[row][k4*4] = v;
            } else {
                int e = t - 128; int row = e >> 2, k4 = e & 3;
                float4 v = *(const float4*)&g_AGG[((size_t)(q0+row)*NH + h1)*CDIM + k0 + k4*4];
                *(float4*)&As1[row][k4*4] = v;
            }
            // Bs: Wv rows k0..k0+15, cols pair*64 .. +64  (256 float4)
            {
                int kk = t >> 4, j4 = t & 15;
                float4 v = *(const float4*)&Wv[(k0+kk)*CDIM + pair*64 + j4*4];
                *(float4*)&Bs[kk][j4*4] = v;
            }
            __syncthreads();
            const float (*Asel)[20] = (tx >= 8) ? As1 : As0;
            #pragma unroll
            for (int kk = 0; kk < 16; kk++) {
                float4 b4 = *(const float4*)&Bs[kk][c0];
                float a0 = Asel[r0+0][kk], a1 = Asel[r0+1][kk];
                acc[0][0] += a0*b4.x; acc[0][1] += a0*b4.y; acc[0][2] += a0*b4.z; acc[0][3] += a0*b4.w;
                acc[1][0] += a1*b4.x; acc[1][1] += a1*b4.y; acc[1][2] += a1*b4.z; acc[1][3] += a1*b4.w;
            }
            __syncthreads();
        }
        // epilogue: X = acc + bv*winb  -> smem
        int hh = pair*2 + (tx >> 3);
        int ch = c0 & 31;
        float4 bvv = *(const float4*)&bv[hh*HD + ch];
        #pragma unroll
        for (int i = 0; i < 2; i++) {
            float w = sWinb[r0+i][hh];
            sX[r0+i][pair*64 + c0 + 0] = acc[i][0] + bvv.x * w;
            sX[r0+i][pair*64 + c0 + 1] = acc[i][1] + bvv.y * w;
            sX[r0+i][pair*64 + c0 + 2] = acc[i][2] + bvv.z * w;
            sX[r0+i][pair*64 + c0 + 3] = acc[i][3] + bvv.w * w;
        }
        __syncthreads();
    }

    // ---------------- stage 2: out = X @ Wout + bout ------------------------
    #pragma unroll 1
    for (int cb = 0; cb < 256; cb += 64) {
        float acc[2][4] = {};
        for (int k0 = 0; k0 < 256; k0 += 16) {
            int kk = t >> 4, j4 = t & 15;
            float4 v = *(const float4*)&Wout[(k0+kk)*CDIM + cb + j4*4];
            *(float4*)&Bs[kk][j4*4] = v;
            __syncthreads();
            #pragma unroll
            for (int kk2 = 0; kk2 < 16; kk2++) {
                float4 b4 = *(const float4*)&Bs[kk2][c0];
                float a0 = sX[r0+0][k0+kk2], a1 = sX[r0+1][k0+kk2];
                acc[0][0] += a0*b4.x; acc[0][1] += a0*b4.y; acc[0][2] += a0*b4.z; acc[0][3] += a0*b4.w;
                acc[1][0] += a1*b4.x; acc[1][1] += a1*b4.y; acc[1][2] += a1*b4.z; acc[1][3] += a1*b4.w;
            }
            __syncthreads();
        }
        float4 bo = *(const float4*)&bout[cb + c0];
        #pragma unroll
        for (int i = 0; i < 2; i++) {
            float4 o;
            o.x = acc[i][0] + bo.x; o.y = acc[i][1] + bo.y;
            o.z = acc[i][2] + bo.z; o.w = acc[i][3] + bo.w;
            *(float4*)&out[(size_t)(q0+r0+i)*CDIM + cb + c0] = o;
        }
    }
}

// ---------------------------------------------------------------------------
extern "C" void kernel_launch(void* const* d_in, const int* in_sizes, int n_in,
                              void* d_out, int out_size) {
    const float* query  = (const float*)d_in[0];
    const float* memory = (const float*)d_in[1];
    const float* refpts = (const float*)d_in[2];
    const float* Wv     = (const float*)d_in[3];
    const float* bv     = (const float*)d_in[4];
    const float* Woff   = (const float*)d_in[5];
    const float* boff   = (const float*)d_in[6];
    const float* Wattn  = (const float*)d_in[7];
    const float* battn  = (const float*)d_in[8];
    const float* Wout   = (const float*)d_in[9];
    const float* bout   = (const float*)d_in[10];
    float* out = (float*)d_out;

    float *pWcat, *pbcat, *pP;
    cudaGetSymbolAddress((void**)&pWcat, g_Wcat);
    cudaGetSymbolAddress((void**)&pbcat, g_bcat);
    cudaGetSymbolAddress((void**)&pP,    g_P);

    // 1. pack offset/attn weight matrices
    k_pack<<<(CDIM*128)/256, 256>>>(Woff, boff, Wattn, battn);
    // 2. P = query @ Wcat + bcat          [8192 x 128]
    k_gemm<<<dim3(NQ/64, 2), 256>>>(query, pWcat, 128, pbcat, pP);
    // 3. fused sampler + dedup gather + per-head aggregation of raw memory
    k_gather<<<NQ, 128>>>(memory, refpts);
    // 4. fused per-head projection + output projection
    k_fuse<<<NQ/32, 256>>>(Wv, bv, Wout, bout, out);
}

// round 6
// speedup vs baseline: 1.4061x; 1.4061x over previous
#include <cuda_runtime.h>
#include <math.h>

// Problem constants (fixed instance)
#define NB    8          // batch
#define LQ    1024       // queries per batch
#define NQ    (NB*LQ)    // 8192 total queries
#define CDIM  256        // d_model
#define NH    8          // heads
#define NP    4          // points
#define HD    32         // head dim
#define IMH   128
#define IMW   128
#define HWPX  (IMH*IMW)  // 16384

// -------- scratch (static __device__; no allocation APIs allowed) --------
__device__ float g_Wcat[CDIM*128];        // [256,128]: cols 0..63 W_off, 64..95 W_attn
__device__ float g_bcat[128];
__device__ float g_P[NQ*128];             // query @ Wcat + bcat
__device__ float g_AGG[NH*NQ*CDIM];       // head-major: AGG[h][q][c]
__device__ float g_WINB[NQ*NH];           // in-bounds weight sums (for b_value)
__device__ float g_X[NQ*CDIM];            // per-head projected output, concat

// ---------------------------------------------------------------------------
// k_pack: assemble [W_off | W_attn | 0] into one 256x128 matrix (+ bias)
// ---------------------------------------------------------------------------
__global__ void k_pack(const float* __restrict__ Woff, const float* __restrict__ boff,
                       const float* __restrict__ Wattn, const float* __restrict__ battn) {
    int t = blockIdx.x * blockDim.x + threadIdx.x;   // 0 .. 256*128-1
    int c = t >> 7, j = t & 127;
    float v = 0.f;
    if (j < 64)      v = Woff[c*64 + j];
    else if (j < 96) v = Wattn[c*32 + (j-64)];
    g_Wcat[c*128 + j] = v;
    if (c == 0) {
        float b = 0.f;
        if (j < 64)      b = boff[j];
        else if (j < 96) b = battn[j-64];
        g_bcat[j] = b;
    }
}

// ---------------------------------------------------------------------------
// k_gemm: C[M=8192, N] = A[8192,256] @ B[256,N] + bias.  64x64 tiles, 256 thr,
// 4x4 microtiles, fully vectorized float4 global loads.
// ---------------------------------------------------------------------------
__global__ __launch_bounds__(256) void k_gemm(const float* __restrict__ A,
                                              const float* __restrict__ B, int N,
                                              const float* __restrict__ bias,
                                              float* __restrict__ Cout) {
    __shared__ float As[64][36];     // pad 36: float4-aligned
    __shared__ float Bs[32][64];
    int t  = threadIdx.x;
    int q0 = blockIdx.x * 64;
    int cb = blockIdx.y * 64;
    int tx = t & 15, ty = t >> 4;
    int c0 = tx * 4, r0 = ty * 4;
    float acc[4][4] = {};
    for (int k0 = 0; k0 < 256; k0 += 32) {
        #pragma unroll
        for (int i = 0; i < 2; i++) {       // 512 float4 A-elems
            int e = t + i*256; int row = e >> 3, k4 = e & 7;
            float4 v = *(const float4*)&A[(q0+row)*256 + k0 + k4*4];
            *(float4*)&As[row][k4*4] = v;
        }
        #pragma unroll
        for (int i = 0; i < 2; i++) {       // 512 float4 B-elems
            int e = t + i*256; int kk = e >> 4, j4 = e & 15;
            float4 v = *(const float4*)&B[(k0+kk)*N + cb + j4*4];
            *(float4*)&Bs[kk][j4*4] = v;
        }
        __syncthreads();
        #pragma unroll
        for (int kk = 0; kk < 32; kk++) {
            float4 b4 = *(const float4*)&Bs[kk][c0];
            float a0 = As[r0+0][kk], a1 = As[r0+1][kk], a2 = As[r0+2][kk], a3 = As[r0+3][kk];
            acc[0][0] += a0*b4.x; acc[0][1] += a0*b4.y; acc[0][2] += a0*b4.z; acc[0][3] += a0*b4.w;
            acc[1][0] += a1*b4.x; acc[1][1] += a1*b4.y; acc[1][2] += a1*b4.z; acc[1][3] += a1*b4.w;
            acc[2][0] += a2*b4.x; acc[2][1] += a2*b4.y; acc[2][2] += a2*b4.z; acc[2][3] += a2*b4.w;
            acc[3][0] += a3*b4.x; acc[3][1] += a3*b4.y; acc[3][2] += a3*b4.z; acc[3][3] += a3*b4.w;
        }
        __syncthreads();
    }
    #pragma unroll
    for (int i = 0; i < 4; i++) {
        float4 o;
        o.x = acc[i][0] + bias[cb+c0+0];
        o.y = acc[i][1] + bias[cb+c0+1];
        o.z = acc[i][2] + bias[cb+c0+2];
        o.w = acc[i][3] + bias[cb+c0+3];
        *(float4*)&Cout[(q0+r0+i)*N + cb + c0] = o;
    }
}

// ---------------------------------------------------------------------------
// k_gather: 2 queries per block (128 thr). Per query:
//  - sampler (32 thr each, 64 total) -> coords + softmax weights
//  - hash-dedup of 128 bilinear corners (2 sequential passes, all threads)
//  - accumulation: 64 threads per query (ALL 128 active), float4 channels,
//    8 head accumulators, MLP=4 row loads
// ---------------------------------------------------------------------------
__global__ __launch_bounds__(128) void k_gather(const float* __restrict__ memory,
                                                const float* __restrict__ ref) {
    __shared__ int   s_key[2][256];
    __shared__ float s_w[2][256][NH];
    __shared__ int   s_list[2][128];
    __shared__ int   s_n[2];
    __shared__ float s_winb[2][NH];
    __shared__ float s_x[2][32], s_y[2][32], s_aw[2][32];

    int t  = threadIdx.x;
    int q0 = blockIdx.x * 2;
    int n  = q0 >> 10;                   // q0 even, 1024/batch -> same batch for both

    #pragma unroll
    for (int qq = 0; qq < 2; qq++) {
        s_key[qq][t] = -1; s_key[qq][t+128] = -1;
        #pragma unroll
        for (int h = 0; h < NH; h++) { s_w[qq][t][h] = 0.f; s_w[qq][t+128][h] = 0.f; }
    }
    if (t < 2)  s_n[t] = 0;
    if (t < 16) s_winb[t>>3][t&7] = 0.f;

    if (t < 64) {    // sampler: qq = t>>5, sample tt = t&31
        int qq = t >> 5, tt = t & 31;
        int q = q0 + qq;
        int h = tt >> 2, p = tt & 3;
        const float* Pq = &g_P[q*128];
        float rx = ref[q*2+0] * (float)IMW - 0.5f;
        float ry = ref[q*2+1] * (float)IMH - 0.5f;
        float a0 = Pq[64+h*4+0], a1 = Pq[64+h*4+1];
        float a2 = Pq[64+h*4+2], a3 = Pq[64+h*4+3];
        float m = fmaxf(fmaxf(a0,a1), fmaxf(a2,a3));
        float e0 = expf(a0-m), e1 = expf(a1-m), e2 = expf(a2-m), e3 = expf(a3-m);
        float inv = 1.f / (e0+e1+e2+e3);
        float ep = (p == 0) ? e0 : (p == 1) ? e1 : (p == 2) ? e2 : e3;
        s_x[qq][tt]  = rx + Pq[h*8 + p*2 + 0];
        s_y[qq][tt]  = ry + Pq[h*8 + p*2 + 1];
        s_aw[qq][tt] = ep * inv;
    }
    __syncthreads();

    // hash insert: one pass per query, all 128 threads (one corner each)
    #pragma unroll
    for (int qq = 0; qq < 2; qq++) {
        int hp = t >> 2, corner = t & 3;
        int h = hp >> 2;
        float x  = s_x[qq][hp], y = s_y[qq][hp], aw = s_aw[qq][hp];
        float fx0 = floorf(x), fy0 = floorf(y);
        int ix = (int)fx0 + (corner & 1);
        int iy = (int)fy0 + (corner >> 1);
        float fx = x - fx0, fy = y - fy0;
        float wx = (corner & 1) ? fx : (1.f - fx);
        float wy = (corner & 2) ? fy : (1.f - fy);
        float w = wx * wy * aw;
        if (ix >= 0 && ix < IMW && iy >= 0 && iy < IMH && w != 0.f) {
            int row = iy * IMW + ix;
            int slot = row & 255;
            while (true) {
                int prev = atomicCAS(&s_key[qq][slot], -1, row);
                if (prev == -1 || prev == row) break;
                slot = (slot + 1) & 255;
            }
            atomicAdd(&s_w[qq][slot][h], w);
            atomicAdd(&s_winb[qq][h], w);
        }
    }
    __syncthreads();
    #pragma unroll
    for (int qq = 0; qq < 2; qq++) {
        if (s_key[qq][t]     != -1) { int pos = atomicAdd(&s_n[qq], 1); s_list[qq][pos] = t; }
        if (s_key[qq][t+128] != -1) { int pos = atomicAdd(&s_n[qq], 1); s_list[qq][pos] = t+128; }
    }
    __syncthreads();

    // accumulation: threads 0-63 -> query q0, 64-127 -> query q0+1
    int qq = t >> 6, tt = t & 63;
    int q  = q0 + qq;
    int c  = tt * 4;
    int nrows = s_n[qq];
    const float* mem = memory + (size_t)n * HWPX * CDIM;
    const int*   key = s_key[qq];
    const float (*wt)[NH] = s_w[qq];
    const int*   lst = s_list[qq];

    float4 acc[NH];
    #pragma unroll
    for (int h = 0; h < NH; h++) acc[h] = make_float4(0.f,0.f,0.f,0.f);

    int i = 0;
    for (; i + 3 < nrows; i += 4) {      // MLP=4
        int s0 = lst[i+0], s1 = lst[i+1], s2 = lst[i+2], s3 = lst[i+3];
        float4 v0 = *(const float4*)&mem[(size_t)key[s0]*CDIM + c];
        float4 v1 = *(const float4*)&mem[(size_t)key[s1]*CDIM + c];
        float4 v2 = *(const float4*)&mem[(size_t)key[s2]*CDIM + c];
        float4 v3 = *(const float4*)&mem[(size_t)key[s3]*CDIM + c];
        #pragma unroll
        for (int h = 0; h < NH; h++) {
            float w0 = wt[s0][h], w1 = wt[s1][h], w2 = wt[s2][h], w3 = wt[s3][h];
            acc[h].x += w0*v0.x + w1*v1.x + w2*v2.x + w3*v3.x;
            acc[h].y += w0*v0.y + w1*v1.y + w2*v2.y + w3*v3.y;
            acc[h].z += w0*v0.z + w1*v1.z + w2*v2.z + w3*v3.z;
            acc[h].w += w0*v0.w + w1*v1.w + w2*v2.w + w3*v3.w;
        }
    }
    for (; i < nrows; i++) {
        int s0 = lst[i];
        float4 v0 = *(const float4*)&mem[(size_t)key[s0]*CDIM + c];
        #pragma unroll
        for (int h = 0; h < NH; h++) {
            float w0 = wt[s0][h];
            acc[h].x += w0*v0.x; acc[h].y += w0*v0.y;
            acc[h].z += w0*v0.z; acc[h].w += w0*v0.w;
        }
    }
    #pragma unroll
    for (int h = 0; h < NH; h++)
        *(float4*)&g_AGG[((size_t)h*NQ + q)*CDIM + c] = acc[h];     // head-major

    if (t < 16) g_WINB[(q0 + (t>>3))*NH + (t&7)] = s_winb[t>>3][t&7];
}

// ---------------------------------------------------------------------------
// k_headproj: per head h (blockIdx.y): X[:, h*32:(h+1)*32] = AGG_h @ Wv_h + bv*winb
// Tile 128 queries x 32 cols, 256 threads, 4x4 microtiles with STRIDED rows
// (r = ty + 32*i) for conflict-free LDS. All global loads float4.
// ---------------------------------------------------------------------------
__global__ __launch_bounds__(256) void k_headproj(const float* __restrict__ Wv,
                                                  const float* __restrict__ bv) {
    __shared__ float As[128][36];    // 18KB
    __shared__ float Bs[32][36];
    int t  = threadIdx.x;
    int q0 = blockIdx.x * 128;
    int h  = blockIdx.y;
    int tx = t & 7, ty = t >> 3;     // 8 x 32
    int c0 = tx * 4;
    const float* Ah = &g_AGG[(size_t)h*NQ*CDIM];
    float acc[4][4] = {};
    for (int k0 = 0; k0 < 256; k0 += 32) {
        #pragma unroll
        for (int i = 0; i < 4; i++) {       // 1024 float4 A-elems
            int e = t + i*256; int row = e >> 3, k4 = e & 7;
            float4 v = *(const float4*)&Ah[(size_t)(q0+row)*CDIM + k0 + k4*4];
            *(float4*)&As[row][k4*4] = v;
        }
        {                                    // 256 float4 B-elems
            int kk = t >> 3, j4 = t & 7;
            float4 v = *(const float4*)&Wv[(k0+kk)*CDIM + h*HD + j4*4];
            *(float4*)&Bs[kk][j4*4] = v;
        }
        __syncthreads();
        #pragma unroll
        for (int kk = 0; kk < 32; kk++) {
            float4 b4 = *(const float4*)&Bs[kk][c0];
            float a0 = As[ty +  0][kk], a1 = As[ty + 32][kk];
            float a2 = As[ty + 64][kk], a3 = As[ty + 96][kk];
            acc[0][0] += a0*b4.x; acc[0][1] += a0*b4.y; acc[0][2] += a0*b4.z; acc[0][3] += a0*b4.w;
            acc[1][0] += a1*b4.x; acc[1][1] += a1*b4.y; acc[1][2] += a1*b4.z; acc[1][3] += a1*b4.w;
            acc[2][0] += a2*b4.x; acc[2][1] += a2*b4.y; acc[2][2] += a2*b4.z; acc[2][3] += a2*b4.w;
            acc[3][0] += a3*b4.x; acc[3][1] += a3*b4.y; acc[3][2] += a3*b4.z; acc[3][3] += a3*b4.w;
        }
        __syncthreads();
    }
    float4 bvv = *(const float4*)&bv[h*HD + c0];
    #pragma unroll
    for (int i = 0; i < 4; i++) {
        int r = q0 + ty + 32*i;
        float wb = g_WINB[r*NH + h];
        float4 o;
        o.x = acc[i][0] + bvv.x * wb;
        o.y = acc[i][1] + bvv.y * wb;
        o.z = acc[i][2] + bvv.z * wb;
        o.w = acc[i][3] + bvv.w * wb;
        *(float4*)&g_X[(size_t)r*CDIM + h*HD + c0] = o;
    }
}

// ---------------------------------------------------------------------------
extern "C" void kernel_launch(void* const* d_in, const int* in_sizes, int n_in,
                              void* d_out, int out_size) {
    const float* query  = (const float*)d_in[0];
    const float* memory = (const float*)d_in[1];
    const float* refpts = (const float*)d_in[2];
    const float* Wv     = (const float*)d_in[3];
    const float* bv     = (const float*)d_in[4];
    const float* Woff   = (const float*)d_in[5];
    const float* boff   = (const float*)d_in[6];
    const float* Wattn  = (const float*)d_in[7];
    const float* battn  = (const float*)d_in[8];
    const float* Wout   = (const float*)d_in[9];
    const float* bout   = (const float*)d_in[10];
    float* out = (float*)d_out;

    float *pWcat, *pbcat, *pP, *pX;
    cudaGetSymbolAddress((void**)&pWcat, g_Wcat);
    cudaGetSymbolAddress((void**)&pbcat, g_bcat);
    cudaGetSymbolAddress((void**)&pP,    g_P);
    cudaGetSymbolAddress((void**)&pX,    g_X);

    // 1. pack offset/attn weight matrices
    k_pack<<<(CDIM*128)/256, 256>>>(Woff, boff, Wattn, battn);
    // 2. P = query @ Wcat + bcat          [8192 x 128]
    k_gemm<<<dim3(NQ/64, 2), 256>>>(query, pWcat, 128, pbcat, pP);
    // 3. fused sampler + dedup gather (2 queries/block), head-major AGG
    k_gather<<<NQ/2, 128>>>(memory, refpts);
    // 4. per-head projection: X[:, h*32:] = AGG_h @ Wv_h + bv*winb
    k_headproj<<<dim3(NQ/128, NH), 256>>>(Wv, bv);
    // 5. out = X @ W_out + b_out          [8192 x 256]
    k_gemm<<<dim3(NQ/64, 4), 256>>>(pX, Wout, 256, bout, out);
}

// round 7
// speedup vs baseline: 1.5270x; 1.0860x over previous
#include <cuda_runtime.h>
#include <math.h>

// Problem constants (fixed instance)
#define NB    8
#define LQ    1024
#define NQ    (NB*LQ)    // 8192
#define CDIM  256
#define NH    8
#define NP    4
#define HD    32
#define IMH   128
#define IMW   128
#define HWPX  (IMH*IMW)

// -------- scratch --------
__device__ float g_Wcat[CDIM*128];
__device__ float g_bcat[128];
__device__ float g_P[NQ*128];
__device__ float g_AGG[NH*NQ*CDIM];       // head-major: AGG[h][q][c]
__device__ float g_WINB[NQ*NH];
__device__ float g_X[NQ*CDIM];

// ---- cp.async helpers ----
__device__ __forceinline__ void cp16(void* smem, const void* g) {
    unsigned saddr = (unsigned)__cvta_generic_to_shared(smem);
    asm volatile("cp.async.ca.shared.global [%0], [%1], 16;" :: "r"(saddr), "l"(g));
}
__device__ __forceinline__ void cp_commit_wait() {
    asm volatile("cp.async.commit_group;");
    asm volatile("cp.async.wait_group 0;");
}

// ---------------------------------------------------------------------------
__global__ void k_pack(const float* __restrict__ Woff, const float* __restrict__ boff,
                       const float* __restrict__ Wattn, const float* __restrict__ battn) {
    int t = blockIdx.x * blockDim.x + threadIdx.x;
    int c = t >> 7, j = t & 127;
    float v = 0.f;
    if (j < 64)      v = Woff[c*64 + j];
    else if (j < 96) v = Wattn[c*32 + (j-64)];
    g_Wcat[c*128 + j] = v;
    if (c == 0) {
        float b = 0.f;
        if (j < 64)      b = boff[j];
        else if (j < 96) b = battn[j-64];
        g_bcat[j] = b;
    }
}

// ---------------------------------------------------------------------------
// k_gemm: C[8192, N] = A[8192,256] @ B[256,N] + bias. 64x64 tiles, 256 thr,
// 4x4 microtiles, cp.async tile loads, occupancy-capped regs.
// ---------------------------------------------------------------------------
__global__ __launch_bounds__(256, 4) void k_gemm(const float* __restrict__ A,
                                                 const float* __restrict__ B, int N,
                                                 const float* __restrict__ bias,
                                                 float* __restrict__ Cout) {
    __shared__ float As[64][36];
    __shared__ float Bs[32][64];
    int t  = threadIdx.x;
    int q0 = blockIdx.x * 64;
    int cb = blockIdx.y * 64;
    int tx = t & 15, ty = t >> 4;
    int c0 = tx * 4, r0 = ty * 4;
    float acc[4][4] = {};
    for (int k0 = 0; k0 < 256; k0 += 32) {
        #pragma unroll
        for (int i = 0; i < 2; i++) {
            int e = t + i*256; int row = e >> 3, k4 = e & 7;
            cp16(&As[row][k4*4], &A[(q0+row)*256 + k0 + k4*4]);
        }
        #pragma unroll
        for (int i = 0; i < 2; i++) {
            int e = t + i*256; int kk = e >> 4, j4 = e & 15;
            cp16(&Bs[kk][j4*4], &B[(k0+kk)*N + cb + j4*4]);
        }
        cp_commit_wait();
        __syncthreads();
        #pragma unroll
        for (int kk = 0; kk < 32; kk++) {
            float4 b4 = *(const float4*)&Bs[kk][c0];
            float a0 = As[r0+0][kk], a1 = As[r0+1][kk], a2 = As[r0+2][kk], a3 = As[r0+3][kk];
            acc[0][0] += a0*b4.x; acc[0][1] += a0*b4.y; acc[0][2] += a0*b4.z; acc[0][3] += a0*b4.w;
            acc[1][0] += a1*b4.x; acc[1][1] += a1*b4.y; acc[1][2] += a1*b4.z; acc[1][3] += a1*b4.w;
            acc[2][0] += a2*b4.x; acc[2][1] += a2*b4.y; acc[2][2] += a2*b4.z; acc[2][3] += a2*b4.w;
            acc[3][0] += a3*b4.x; acc[3][1] += a3*b4.y; acc[3][2] += a3*b4.z; acc[3][3] += a3*b4.w;
        }
        __syncthreads();
    }
    #pragma unroll
    for (int i = 0; i < 4; i++) {
        float4 o;
        o.x = acc[i][0] + bias[cb+c0+0];
        o.y = acc[i][1] + bias[cb+c0+1];
        o.z = acc[i][2] + bias[cb+c0+2];
        o.w = acc[i][3] + bias[cb+c0+3];
        *(float4*)&Cout[(q0+r0+i)*N + cb + c0] = o;
    }
}

// ---------------------------------------------------------------------------
// k_gather: 2 queries/block (128 thr). Vectorized weight loads (2x LDS.128
// per row), shfl-reduced winb, MLP=4 row loads, head-major AGG output.
// ---------------------------------------------------------------------------
__global__ __launch_bounds__(128) void k_gather(const float* __restrict__ memory,
                                                const float* __restrict__ ref) {
    __shared__ int   s_key[2][256];
    __shared__ __align__(16) float s_w[2][256][NH];
    __shared__ int   s_list[2][128];
    __shared__ int   s_n[2];
    __shared__ float s_winb[2][NH];
    __shared__ float s_x[2][32], s_y[2][32], s_aw[2][32];

    int t  = threadIdx.x;
    int q0 = blockIdx.x * 2;
    int n  = q0 >> 10;

    #pragma unroll
    for (int qq = 0; qq < 2; qq++) {
        s_key[qq][t] = -1; s_key[qq][t+128] = -1;
        *(float4*)&s_w[qq][t][0]     = make_float4(0.f,0.f,0.f,0.f);
        *(float4*)&s_w[qq][t][4]     = make_float4(0.f,0.f,0.f,0.f);
        *(float4*)&s_w[qq][t+128][0] = make_float4(0.f,0.f,0.f,0.f);
        *(float4*)&s_w[qq][t+128][4] = make_float4(0.f,0.f,0.f,0.f);
    }
    if (t < 2)  s_n[t] = 0;
    if (t < 16) s_winb[t>>3][t&7] = 0.f;

    if (t < 64) {    // sampler
        int qq = t >> 5, tt = t & 31;
        int q = q0 + qq;
        int h = tt >> 2, p = tt & 3;
        const float* Pq = &g_P[q*128];
        float rx = ref[q*2+0] * (float)IMW - 0.5f;
        float ry = ref[q*2+1] * (float)IMH - 0.5f;
        float a0 = Pq[64+h*4+0], a1 = Pq[64+h*4+1];
        float a2 = Pq[64+h*4+2], a3 = Pq[64+h*4+3];
        float m = fmaxf(fmaxf(a0,a1), fmaxf(a2,a3));
        float e0 = expf(a0-m), e1 = expf(a1-m), e2 = expf(a2-m), e3 = expf(a3-m);
        float inv = 1.f / (e0+e1+e2+e3);
        float ep = (p == 0) ? e0 : (p == 1) ? e1 : (p == 2) ? e2 : e3;
        s_x[qq][tt]  = rx + Pq[h*8 + p*2 + 0];
        s_y[qq][tt]  = ry + Pq[h*8 + p*2 + 1];
        s_aw[qq][tt] = ep * inv;
    }
    __syncthreads();

    // corner expansion + hash insert (two passes, all 128 threads)
    #pragma unroll
    for (int qq = 0; qq < 2; qq++) {
        int hp = t >> 2, corner = t & 3;
        int h = hp >> 2;                       // = t>>4
        float x  = s_x[qq][hp], y = s_y[qq][hp], aw = s_aw[qq][hp];
        float fx0 = floorf(x), fy0 = floorf(y);
        int ix = (int)fx0 + (corner & 1);
        int iy = (int)fy0 + (corner >> 1);
        float fx = x - fx0, fy = y - fy0;
        float wx = (corner & 1) ? fx : (1.f - fx);
        float wy = (corner & 2) ? fy : (1.f - fy);
        float w = wx * wy * aw;
        bool inb = (ix >= 0 && ix < IMW && iy >= 0 && iy < IMH);
        if (inb && w != 0.f) {
            int row = iy * IMW + ix;
            int slot = row & 255;
            while (true) {
                int prev = atomicCAS(&s_key[qq][slot], -1, row);
                if (prev == -1 || prev == row) break;
                slot = (slot + 1) & 255;
            }
            atomicAdd(&s_w[qq][slot][h], w);
        }
        // winb: 16-lane segmented reduction (h constant per segment), 8 atomics
        float wr = inb ? w : 0.f;
        #pragma unroll
        for (int o = 8; o; o >>= 1) wr += __shfl_xor_sync(0xffffffffu, wr, o, 16);
        if ((t & 15) == 0) atomicAdd(&s_winb[qq][h], wr);
    }
    __syncthreads();
    #pragma unroll
    for (int qq = 0; qq < 2; qq++) {
        if (s_key[qq][t]     != -1) { int pos = atomicAdd(&s_n[qq], 1); s_list[qq][pos] = t; }
        if (s_key[qq][t+128] != -1) { int pos = atomicAdd(&s_n[qq], 1); s_list[qq][pos] = t+128; }
    }
    __syncthreads();

    // accumulation: threads 0-63 -> q0, 64-127 -> q0+1
    int qq = t >> 6, tt = t & 63;
    int q  = q0 + qq;
    int c  = tt * 4;
    int nrows = s_n[qq];
    const float* mem = memory + (size_t)n * HWPX * CDIM;
    const int*   key = s_key[qq];
    const float (*wt)[NH] = s_w[qq];
    const int*   lst = s_list[qq];

    float4 acc[NH];
    #pragma unroll
    for (int h = 0; h < NH; h++) acc[h] = make_float4(0.f,0.f,0.f,0.f);

    int i = 0;
    for (; i + 3 < nrows; i += 4) {
        int s0 = lst[i+0], s1 = lst[i+1], s2 = lst[i+2], s3 = lst[i+3];
        float4 v0 = *(const float4*)&mem[(size_t)key[s0]*CDIM + c];
        float4 v1 = *(const float4*)&mem[(size_t)key[s1]*CDIM + c];
        float4 v2 = *(const float4*)&mem[(size_t)key[s2]*CDIM + c];
        float4 v3 = *(const float4*)&mem[(size_t)key[s3]*CDIM + c];
        float4 wl0 = *(const float4*)&wt[s0][0], wh0 = *(const float4*)&wt[s0][4];
        float4 wl1 = *(const float4*)&wt[s1][0], wh1 = *(const float4*)&wt[s1][4];
        float4 wl2 = *(const float4*)&wt[s2][0], wh2 = *(const float4*)&wt[s2][4];
        float4 wl3 = *(const float4*)&wt[s3][0], wh3 = *(const float4*)&wt[s3][4];
        float w0[8] = {wl0.x,wl0.y,wl0.z,wl0.w, wh0.x,wh0.y,wh0.z,wh0.w};
        float w1[8] = {wl1.x,wl1.y,wl1.z,wl1.w, wh1.x,wh1.y,wh1.z,wh1.w};
        float w2[8] = {wl2.x,wl2.y,wl2.z,wl2.w, wh2.x,wh2.y,wh2.z,wh2.w};
        float w3[8] = {wl3.x,wl3.y,wl3.z,wl3.w, wh3.x,wh3.y,wh3.z,wh3.w};
        #pragma unroll
        for (int h = 0; h < NH; h++) {
            acc[h].x += w0[h]*v0.x + w1[h]*v1.x + w2[h]*v2.x + w3[h]*v3.x;
            acc[h].y += w0[h]*v0.y + w1[h]*v1.y + w2[h]*v2.y + w3[h]*v3.y;
            acc[h].z += w0[h]*v0.z + w1[h]*v1.z + w2[h]*v2.z + w3[h]*v3.z;
            acc[h].w += w0[h]*v0.w + w1[h]*v1.w + w2[h]*v2.w + w3[h]*v3.w;
        }
    }
    for (; i < nrows; i++) {
        int s0 = lst[i];
        float4 v0 = *(const float4*)&mem[(size_t)key[s0]*CDIM + c];
        float4 wl = *(const float4*)&wt[s0][0], wh = *(const float4*)&wt[s0][4];
        float w8[8] = {wl.x,wl.y,wl.z,wl.w, wh.x,wh.y,wh.z,wh.w};
        #pragma unroll
        for (int h = 0; h < NH; h++) {
            acc[h].x += w8[h]*v0.x; acc[h].y += w8[h]*v0.y;
            acc[h].z += w8[h]*v0.z; acc[h].w += w8[h]*v0.w;
        }
    }
    #pragma unroll
    for (int h = 0; h < NH; h++)
        *(float4*)&g_AGG[((size_t)h*NQ + q)*CDIM + c] = acc[h];

    if (t < 16) g_WINB[(q0 + (t>>3))*NH + (t&7)] = s_winb[t>>3][t&7];
}

// ---------------------------------------------------------------------------
// k_headproj2: head-PAIR tiles. Block computes X[q0:q0+64, pair*64:(pair+1)*64]
// where cols 0-31 of the tile use AGG_{2p}, cols 32-63 use AGG_{2p+1}.
// k_gemm skeleton: 256 thr, 4x4 microtiles, cp.async, two A tiles.
// ---------------------------------------------------------------------------
__global__ __launch_bounds__(256, 4) void k_headproj2(const float* __restrict__ Wv,
                                                      const float* __restrict__ bv) {
    __shared__ float As0[64][36];
    __shared__ float As1[64][36];
    __shared__ float Bs[32][64];
    int t    = threadIdx.x;
    int q0   = blockIdx.x * 64;
    int pair = blockIdx.y;
    int h0   = pair*2, h1 = pair*2 + 1;
    int tx = t & 15, ty = t >> 4;
    int c0 = tx * 4, r0 = ty * 4;
    const float* A0 = &g_AGG[(size_t)h0*NQ*CDIM];
    const float* A1 = &g_AGG[(size_t)h1*NQ*CDIM];
    float acc[4][4] = {};
    for (int k0 = 0; k0 < 256; k0 += 32) {
        #pragma unroll
        for (int i = 0; i < 2; i++) {
            int e = t + i*256; int row = e >> 3, k4 = e & 7;
            cp16(&As0[row][k4*4], &A0[(size_t)(q0+row)*CDIM + k0 + k4*4]);
            cp16(&As1[row][k4*4], &A1[(size_t)(q0+row)*CDIM + k0 + k4*4]);
        }
        #pragma unroll
        for (int i = 0; i < 2; i++) {
            int e = t + i*256; int kk = e >> 4, j4 = e & 15;
            cp16(&Bs[kk][j4*4], &Wv[(k0+kk)*CDIM + pair*64 + j4*4]);
        }
        cp_commit_wait();
        __syncthreads();
        const float (*Asel)[36] = (tx >= 8) ? As1 : As0;
        #pragma unroll
        for (int kk = 0; kk < 32; kk++) {
            float4 b4 = *(const float4*)&Bs[kk][c0];
            float a0 = Asel[r0+0][kk], a1 = Asel[r0+1][kk];
            float a2 = Asel[r0+2][kk], a3 = Asel[r0+3][kk];
            acc[0][0] += a0*b4.x; acc[0][1] += a0*b4.y; acc[0][2] += a0*b4.z; acc[0][3] += a0*b4.w;
            acc[1][0] += a1*b4.x; acc[1][1] += a1*b4.y; acc[1][2] += a1*b4.z; acc[1][3] += a1*b4.w;
            acc[2][0] += a2*b4.x; acc[2][1] += a2*b4.y; acc[2][2] += a2*b4.z; acc[2][3] += a2*b4.w;
            acc[3][0] += a3*b4.x; acc[3][1] += a3*b4.y; acc[3][2] += a3*b4.z; acc[3][3] += a3*b4.w;
        }
        __syncthreads();
    }
    int h  = pair*2 + (c0 >> 5);         // which head this column group belongs to
    int ch = c0 & 31;
    float4 bvv = *(const float4*)&bv[h*HD + ch];
    #pragma unroll
    for (int i = 0; i < 4; i++) {
        int r = q0 + r0 + i;
        float wb = g_WINB[r*NH + h];
        float4 o;
        o.x = acc[i][0] + bvv.x * wb;
        o.y = acc[i][1] + bvv.y * wb;
        o.z = acc[i][2] + bvv.z * wb;
        o.w = acc[i][3] + bvv.w * wb;
        *(float4*)&g_X[(size_t)r*CDIM + pair*64 + c0] = o;
    }
}

// ---------------------------------------------------------------------------
extern "C" void kernel_launch(void* const* d_in, const int* in_sizes, int n_in,
                              void* d_out, int out_size) {
    const float* query  = (const float*)d_in[0];
    const float* memory = (const float*)d_in[1];
    const float* refpts = (const float*)d_in[2];
    const float* Wv     = (const float*)d_in[3];
    const float* bv     = (const float*)d_in[4];
    const float* Woff   = (const float*)d_in[5];
    const float* boff   = (const float*)d_in[6];
    const float* Wattn  = (const float*)d_in[7];
    const float* battn  = (const float*)d_in[8];
    const float* Wout   = (const float*)d_in[9];
    const float* bout   = (const float*)d_in[10];
    float* out = (float*)d_out;

    float *pWcat, *pbcat, *pP, *pX;
    cudaGetSymbolAddress((void**)&pWcat, g_Wcat);
    cudaGetSymbolAddress((void**)&pbcat, g_bcat);
    cudaGetSymbolAddress((void**)&pP,    g_P);
    cudaGetSymbolAddress((void**)&pX,    g_X);

    k_pack<<<(CDIM*128)/256, 256>>>(Woff, boff, Wattn, battn);
    k_gemm<<<dim3(NQ/64, 2), 256>>>(query, pWcat, 128, pbcat, pP);
    k_gather<<<NQ/2, 128>>>(memory, refpts);
    k_headproj2<<<dim3(NQ/64, 4), 256>>>(Wv, bv);
    k_gemm<<<dim3(NQ/64, 4), 256>>>(pX, Wout, 256, bout, out);
}